// round 16
// baseline (speedup 1.0000x reference)
#include <cuda_runtime.h>
#include <math.h>

#define NN 50000
#define NE 400000
#define NB 196   // ceil(NN/256) scan blocks

// ---------------- scratch layout (float/int aliased units of 4B) ----------
#define O_ECNT   0LL                      // int[NN]  (zeroed by memset)
#define O_GSUM   (O_ECNT + NN)            // float[64] (zeroed)
#define ZEND     (O_GSUM + 64)
#define O_GATE   (ZEND)
#define O_DIS    (O_GATE + 4)
#define O_OFF    (O_DIS  + NN)            // int[NN+1]
#define O_CUR    (O_OFF  + NN + 8)        // int[NN]
#define O_SRC    (O_CUR  + NN)            // int[NE]
#define O_BSUM   (O_SRC  + NE)            // int[256]
#define O_BOFF   (O_BSUM + 256)           // int[256]
#define O_GCNXH  (O_BOFF + 256)
#define O_GCNH1  (O_GCNXH + (long long)NN*64)
#define O_GCNH2  (O_GCNH1 + (long long)NN*64)
#define O_AGG2   (O_GCNH2 + (long long)NN*64)
#define O_GATH1  (O_AGG2  + (long long)NN*64)
#define O_AS1    (O_GATH1 + (long long)NN*256)
#define O_AD1    (O_AS1   + (long long)NN*4)
#define O_GAGG1  (O_AD1   + (long long)NN*4)
#define O_GATH2  (O_GAGG1 + (long long)NN*256)
#define O_AS2    (O_GATH2 + (long long)NN*64)
#define O_AD2    (O_AS2   + NN)
#define O_GAGG2  (O_AD2   + NN)
#define O_SXR    (O_GAGG2 + (long long)NN*64)
#define O_SMEAN  (O_SXR   + (long long)NN*64)
#define O_SML    (O_SMEAN + (long long)NN*64)
#define O_SH1    (O_SML   + (long long)NN*64)
#define O_SMEAN2 (O_SH1   + (long long)NN*64)
#define O_SML2   (O_SMEAN2+ (long long)NN*64)
#define O_SXR2   (O_SML2  + (long long)NN*64)
#define O_SOUT   (O_SXR2  + (long long)NN*64)
#define SZ_TOTAL (O_SOUT  + (long long)NN*64)

__device__ __align__(256) float g_buf[SZ_TOTAL];

__device__ __forceinline__ float lrelu(float x) { return x > 0.f ? x : 0.2f * x; }

// packed f32x2 FMA (Blackwell; ptxas never emits FFMA2 from C++)
#define FMA2(d, a, b) asm volatile("fma.rn.f32x2 %0, %1, %2, %0;" : "+l"(d) : "l"(a), "l"(b))
#define PACK2(p, a)   asm volatile("mov.b64 %0, {%1, %1};" : "=l"(p) : "f"(a))

// ================= CSR build =================
__global__ void degree_kernel(const int* __restrict__ col, int* __restrict__ ecnt) {
    int e = blockIdx.x * blockDim.x + threadIdx.x;
    if (e < NE) atomicAdd(&ecnt[col[e]], 1);
}

__global__ void scan_bsum(const int* __restrict__ ecnt, int* __restrict__ bsum) {
    __shared__ int s[256];
    int i = blockIdx.x * 256 + threadIdx.x;
    s[threadIdx.x] = (i < NN) ? ecnt[i] : 0;
    __syncthreads();
    for (int o = 128; o > 0; o >>= 1) {
        if (threadIdx.x < o) s[threadIdx.x] += s[threadIdx.x + o];
        __syncthreads();
    }
    if (threadIdx.x == 0) bsum[blockIdx.x] = s[0];
}

__global__ void scan_boff(const int* __restrict__ bsum, int* __restrict__ boff) {
    __shared__ int s[256];
    int t = threadIdx.x;
    int v = (t < NB) ? bsum[t] : 0;
    s[t] = v;
    __syncthreads();
    for (int o = 1; o < 256; o <<= 1) {
        int x = (t >= o) ? s[t - o] : 0;
        __syncthreads();
        s[t] += x;
        __syncthreads();
    }
    boff[t] = s[t] - v;   // exclusive
}

__global__ void scan_final(const int* __restrict__ ecnt, const int* __restrict__ boff,
                           int* __restrict__ off, int* __restrict__ cursor) {
    __shared__ int s[256];
    int t = threadIdx.x;
    int i = blockIdx.x * 256 + t;
    int v = (i < NN) ? ecnt[i] : 0;
    s[t] = v;
    __syncthreads();
    for (int o = 1; o < 256; o <<= 1) {
        int x = (t >= o) ? s[t - o] : 0;
        __syncthreads();
        s[t] += x;
        __syncthreads();
    }
    if (i < NN) { off[i] = boff[blockIdx.x] + s[t] - v; cursor[i] = 0; }
    if (i == 0) off[NN] = NE;
}

__global__ void scatter_kernel(const int* __restrict__ row, const int* __restrict__ col,
                               const int* __restrict__ off, int* __restrict__ cursor,
                               int* __restrict__ srcv) {
    int e = blockIdx.x * 256 + threadIdx.x;
    if (e >= NE) return;
    int c = col[e];
    int p = off[c] + atomicAdd(&cursor[c], 1);
    srcv[p] = row[e];
}

__global__ void dis_kernel(const int* __restrict__ off, float* __restrict__ dis) {
    int i = blockIdx.x * blockDim.x + threadIdx.x;
    if (i < NN) dis[i] = rsqrtf((float)(off[i + 1] - off[i]) + 1.f);
}

// ================= gate =================
__global__ void colsum_kernel(const float* __restrict__ x, float* __restrict__ gsum) {
    __shared__ float4 s[256];
    int t = threadIdx.x;
    int c4 = t & 15, rg = t >> 4;
    float4 acc = {0.f, 0.f, 0.f, 0.f};
    for (int i = blockIdx.x * 16 + rg; i < NN; i += gridDim.x * 16) {
        float4 v = ((const float4*)x)[i * 16 + c4];
        acc.x += v.x; acc.y += v.y; acc.z += v.z; acc.w += v.w;
    }
    s[t] = acc;
    __syncthreads();
    for (int st = 128; st >= 16; st >>= 1) {
        if (t < st) {
            s[t].x += s[t + st].x; s[t].y += s[t + st].y;
            s[t].z += s[t + st].z; s[t].w += s[t + st].w;
        }
        __syncthreads();
    }
    if (t < 16) {
        float4 v = s[t];
        atomicAdd(&gsum[t * 4 + 0], v.x);
        atomicAdd(&gsum[t * 4 + 1], v.y);
        atomicAdd(&gsum[t * 4 + 2], v.z);
        atomicAdd(&gsum[t * 4 + 3], v.w);
    }
}

__global__ void gate_kernel(const float* __restrict__ gsum, float* __restrict__ gate,
                            const float* __restrict__ w1, const float* __restrict__ b1,
                            const float* __restrict__ w2, const float* __restrict__ b2) {
    __shared__ float gm[64], hid[64], o[3];
    int t = threadIdx.x;
    gm[t] = gsum[t] / (float)NN;
    __syncthreads();
    float a = b1[t];
    for (int k = 0; k < 64; k++) a += gm[k] * w1[k * 64 + t];
    hid[t] = fmaxf(a, 0.f);
    __syncthreads();
    if (t < 3) {
        float s = b2[t];
        for (int k = 0; k < 64; k++) s += hid[k] * w2[k * 3 + t];
        o[t] = s;
    }
    __syncthreads();
    if (t == 0) {
        float mx = fmaxf(o[0], fmaxf(o[1], o[2]));
        float e0 = expf(o[0] - mx), e1 = expf(o[1] - mx), e2 = expf(o[2] - mx);
        float s = e0 + e1 + e2;
        gate[0] = e0 / s; gate[1] = e1 / s; gate[2] = e2 / s;
    }
}

// ================= GEMM body: 128x64 tile, 256 thr, FFMA2 inner loop =======
// thread: 4 rows (rowg=t>>3) x 8 cols (colg=t&7), acc packed as u64 pairs.
// sA padded to 65 floats/row -> conflict-free broadcast reads.
__device__ __forceinline__ void gemm_body(
        const float* __restrict__ A, const float* __restrict__ W,
        float* __restrict__ C, int n, int din, int dout, int bx, int by) {
    __shared__ float sW[64 * 64];
    __shared__ float sA[128 * 65];
    int t = threadIdx.x;
    int colg = t & 7;        // 8 col groups of 8 cols
    int rowg = t >> 3;       // 32 row groups of 4 rows
    int r0 = bx * 128;
    int cb = by * 64;
    unsigned sWu = (unsigned)__cvta_generic_to_shared(sW);
    unsigned long long acc[4][4];
#pragma unroll
    for (int i = 0; i < 4; i++)
#pragma unroll
        for (int j = 0; j < 4; j++) acc[i][j] = 0ull;

    for (int k0 = 0; k0 < din; k0 += 64) {
#pragma unroll
        for (int u = 0; u < 4; u++) {
            int i = t + u * 256;
            int kk = i >> 4, cc = i & 15;
            ((float4*)sW)[i] = ((const float4*)(W + (long long)(k0 + kk) * dout + cb))[cc];
        }
#pragma unroll
        for (int u = 0; u < 8; u++) {
            int i = t + u * 256;
            int rr = i >> 4, kk = i & 15;
            float4 v = make_float4(0.f, 0.f, 0.f, 0.f);
            if (r0 + rr < n) v = ((const float4*)(A + (long long)(r0 + rr) * din + k0))[kk];
            float* dst = sA + rr * 65 + kk * 4;
            dst[0] = v.x; dst[1] = v.y; dst[2] = v.z; dst[3] = v.w;
        }
        __syncthreads();
#pragma unroll 8
        for (int k = 0; k < 64; k++) {
            unsigned long long w0, w1, w2, w3;
            unsigned waddr = sWu + (unsigned)((k * 64 + colg * 8) * 4);
            asm volatile("ld.shared.v2.u64 {%0,%1}, [%2];" : "=l"(w0), "=l"(w1) : "r"(waddr));
            asm volatile("ld.shared.v2.u64 {%0,%1}, [%2];" : "=l"(w2), "=l"(w3) : "r"(waddr + 16));
            const float* arow = sA + (rowg * 4) * 65 + k;
#pragma unroll
            for (int r = 0; r < 4; r++) {
                unsigned long long ap;
                PACK2(ap, arow[r * 65]);
                FMA2(acc[r][0], ap, w0);
                FMA2(acc[r][1], ap, w1);
                FMA2(acc[r][2], ap, w2);
                FMA2(acc[r][3], ap, w3);
            }
        }
        __syncthreads();
    }
#pragma unroll
    for (int r = 0; r < 4; r++) {
        int row = r0 + rowg * 4 + r;
        if (row < n) {
            ulonglong2* dst = (ulonglong2*)(C + (long long)row * dout + cb + colg * 8);
            dst[0] = make_ulonglong2(acc[r][0], acc[r][1]);
            dst[1] = make_ulonglong2(acc[r][2], acc[r][3]);
        }
    }
}

__global__ void __launch_bounds__(256) gemm_tile(
        const float* __restrict__ A, const float* __restrict__ W,
        float* __restrict__ C, int n, int din, int dout) {
    gemm_body(A, W, C, n, din, dout, blockIdx.x, blockIdx.y);
}

// fused: the three independent x-transforms in one launch (blockIdx.y dispatch)
__global__ void __launch_bounds__(256) gemm_x3(
        const float* __restrict__ x,
        const float* __restrict__ w_gcn, float* __restrict__ o_gcn,
        const float* __restrict__ w_gat, float* __restrict__ o_gat,
        const float* __restrict__ w_sage, float* __restrict__ o_sage) {
    int y = blockIdx.y;
    if (y == 0)      gemm_body(x, w_gcn,  o_gcn,  NN, 64, 64,  blockIdx.x, 0);
    else if (y <= 4) gemm_body(x, w_gat,  o_gat,  NN, 64, 256, blockIdx.x, y - 1);
    else             gemm_body(x, w_sage, o_sage, NN, 64, 64,  blockIdx.x, 0);
}

// fused: the two independent SAGE layer-2 GEMMs
__global__ void __launch_bounds__(256) gemm_sage2(
        const float* __restrict__ smean2, const float* __restrict__ wl2, float* __restrict__ sml2,
        const float* __restrict__ sh1,    const float* __restrict__ wr2, float* __restrict__ sxr2) {
    if (blockIdx.y == 0) gemm_body(smean2, wl2, sml2, NN, 64, 64, blockIdx.x, 0);
    else                 gemm_body(sh1,    wr2, sxr2, NN, 64, 64, blockIdx.x, 0);
}

// ================= per-node aggregations (warp per node) =================
template <int EPI>
__global__ void gcn_node(const int* __restrict__ off, const int* __restrict__ srcv,
                         const float* __restrict__ dis, const float* __restrict__ h,
                         float* __restrict__ out, const float* __restrict__ b,
                         const float* __restrict__ gamma, const float* __restrict__ beta) {
    int w = (blockIdx.x * blockDim.x + threadIdx.x) >> 5;
    int l = threadIdx.x & 31;
    if (w >= NN) return;
    int beg = off[w], end = off[w + 1];
    float dn = dis[w];
    const float2* h2 = (const float2*)h;
    float2 acc = make_float2(0.f, 0.f);
    for (int p = beg; p < end; p++) {
        int s = srcv[p];
        float ds = dis[s];
        float2 v = h2[s * 32 + l];
        acc.x += v.x * ds; acc.y += v.y * ds;
    }
    float2 hs = h2[w * 32 + l];
    acc.x = (acc.x + dn * hs.x) * dn;
    acc.y = (acc.y + dn * hs.y) * dn;
    if (EPI) {
        float sc = rsqrtf(1.f + 1e-5f);
        float b0 = b[l * 2], b1 = b[l * 2 + 1];
        float g0 = gamma[l * 2] * sc, g1 = gamma[l * 2 + 1] * sc;
        float t0 = beta[l * 2], t1 = beta[l * 2 + 1];
        acc.x = fmaxf((acc.x + b0) * g0 + t0, 0.f);
        acc.y = fmaxf((acc.y + b1) * g1 + t1, 0.f);
    }
    ((float2*)out)[w * 32 + l] = acc;
}

__global__ void gat_att1(const float* __restrict__ gath1,
                         float* __restrict__ as1, float* __restrict__ ad1,
                         const float* __restrict__ asrc, const float* __restrict__ adst) {
    int t = threadIdx.x;
    int w = t >> 5, l = t & 31;
    int n = blockIdx.x * 8 + w;
    const float4* g4 = (const float4*)(gath1 + (long long)n * 256);
    float4 a = g4[l * 2], b = g4[l * 2 + 1];
    int h = l >> 3;
    int offv = (l & 7) * 8;
    const float* As = asrc + h * 64 + offv;
    const float* Ad = adst + h * 64 + offv;
    float ss = a.x*As[0] + a.y*As[1] + a.z*As[2] + a.w*As[3]
             + b.x*As[4] + b.y*As[5] + b.z*As[6] + b.w*As[7];
    float sd = a.x*Ad[0] + a.y*Ad[1] + a.z*Ad[2] + a.w*Ad[3]
             + b.x*Ad[4] + b.y*Ad[5] + b.z*Ad[6] + b.w*Ad[7];
    ss += __shfl_xor_sync(0xffffffffu, ss, 1);
    sd += __shfl_xor_sync(0xffffffffu, sd, 1);
    ss += __shfl_xor_sync(0xffffffffu, ss, 2);
    sd += __shfl_xor_sync(0xffffffffu, sd, 2);
    ss += __shfl_xor_sync(0xffffffffu, ss, 4);
    sd += __shfl_xor_sync(0xffffffffu, sd, 4);
    if ((l & 7) == 0) { as1[n * 4 + h] = ss; ad1[n * 4 + h] = sd; }
}

__device__ __forceinline__ float4 exp_lrelu4(float4 s, float4 d) {
    float4 o;
    o.x = __expf(lrelu(s.x + d.x));
    o.y = __expf(lrelu(s.y + d.y));
    o.z = __expf(lrelu(s.z + d.z));
    o.w = __expf(lrelu(s.w + d.w));
    return o;
}
__device__ __forceinline__ float sel4(float4 v, int h) {
    float r = v.x;
    r = (h == 1) ? v.y : r;
    r = (h == 2) ? v.z : r;
    r = (h == 3) ? v.w : r;
    return r;
}

__global__ void gat1_node(const int* __restrict__ off, const int* __restrict__ srcv,
                          const float* __restrict__ as1, const float* __restrict__ ad1,
                          const float* __restrict__ gh, float* __restrict__ out,
                          const float* __restrict__ bias) {
    int w = (blockIdx.x * blockDim.x + threadIdx.x) >> 5;
    int l = threadIdx.x & 31;
    if (w >= NN) return;
    int beg = off[w], end = off[w + 1];
    const float4* as4 = (const float4*)as1;
    float4 adn = ((const float4*)ad1)[w];
    float4 ds = make_float4(0.f, 0.f, 0.f, 0.f);
    for (int p = beg + l; p < end; p += 32) {
        float4 e4 = exp_lrelu4(as4[srcv[p]], adn);
        ds.x += e4.x; ds.y += e4.y; ds.z += e4.z; ds.w += e4.w;
    }
#pragma unroll
    for (int o = 16; o > 0; o >>= 1) {
        ds.x += __shfl_xor_sync(0xffffffffu, ds.x, o);
        ds.y += __shfl_xor_sync(0xffffffffu, ds.y, o);
        ds.z += __shfl_xor_sync(0xffffffffu, ds.z, o);
        ds.w += __shfl_xor_sync(0xffffffffu, ds.w, o);
    }
    float4 eself = exp_lrelu4(as4[w], adn);
    ds.x += eself.x; ds.y += eself.y; ds.z += eself.z; ds.w += eself.w;
    int h = l >> 3;
    float rden = 1.f / sel4(ds, h);
    float adh = sel4(adn, h);
    float4 a0 = make_float4(0.f, 0.f, 0.f, 0.f), a1 = a0;
    for (int p = beg; p < end; p++) {
        int s = srcv[p];
        float e = __expf(lrelu(sel4(as4[s], h) + adh));
        float alpha = e * rden;
        const float4* gr = (const float4*)(gh + (long long)s * 256) + l * 2;
        float4 v0 = gr[0], v1 = gr[1];
        a0.x += alpha * v0.x; a0.y += alpha * v0.y; a0.z += alpha * v0.z; a0.w += alpha * v0.w;
        a1.x += alpha * v1.x; a1.y += alpha * v1.y; a1.z += alpha * v1.z; a1.w += alpha * v1.w;
    }
    {
        float alpha = sel4(eself, h) * rden;
        const float4* gr = (const float4*)(gh + (long long)w * 256) + l * 2;
        float4 v0 = gr[0], v1 = gr[1];
        a0.x += alpha * v0.x; a0.y += alpha * v0.y; a0.z += alpha * v0.z; a0.w += alpha * v0.w;
        a1.x += alpha * v1.x; a1.y += alpha * v1.y; a1.z += alpha * v1.z; a1.w += alpha * v1.w;
    }
    const float4* b4 = (const float4*)bias + l * 2;
    float4 bb0 = b4[0], bb1 = b4[1];
    a0.x += bb0.x; a0.y += bb0.y; a0.z += bb0.z; a0.w += bb0.w;
    a1.x += bb1.x; a1.y += bb1.y; a1.z += bb1.z; a1.w += bb1.w;
    a0.x = a0.x > 0.f ? a0.x : (expf(a0.x) - 1.f);
    a0.y = a0.y > 0.f ? a0.y : (expf(a0.y) - 1.f);
    a0.z = a0.z > 0.f ? a0.z : (expf(a0.z) - 1.f);
    a0.w = a0.w > 0.f ? a0.w : (expf(a0.w) - 1.f);
    a1.x = a1.x > 0.f ? a1.x : (expf(a1.x) - 1.f);
    a1.y = a1.y > 0.f ? a1.y : (expf(a1.y) - 1.f);
    a1.z = a1.z > 0.f ? a1.z : (expf(a1.z) - 1.f);
    a1.w = a1.w > 0.f ? a1.w : (expf(a1.w) - 1.f);
    float4* o4 = (float4*)(out + (long long)w * 256) + l * 2;
    o4[0] = a0; o4[1] = a1;
}

__global__ void gat_att2(const float* __restrict__ gath2,
                         float* __restrict__ as2, float* __restrict__ ad2,
                         const float* __restrict__ asrc, const float* __restrict__ adst) {
    int t = threadIdx.x;
    int w = t >> 5, l = t & 31;
    int n = blockIdx.x * 8 + w;
    float v0 = gath2[n * 64 + l], v1 = gath2[n * 64 + 32 + l];
    float ss = v0 * asrc[l] + v1 * asrc[32 + l];
    float sd = v0 * adst[l] + v1 * adst[32 + l];
    for (int o = 16; o > 0; o >>= 1) {
        ss += __shfl_xor_sync(0xffffffffu, ss, o);
        sd += __shfl_xor_sync(0xffffffffu, sd, o);
    }
    if (l == 0) { as2[n] = ss; ad2[n] = sd; }
}

__global__ void gat2_node(const int* __restrict__ off, const int* __restrict__ srcv,
                          const float* __restrict__ as2, const float* __restrict__ ad2,
                          const float* __restrict__ gh, float* __restrict__ out) {
    int w = (blockIdx.x * blockDim.x + threadIdx.x) >> 5;
    int l = threadIdx.x & 31;
    if (w >= NN) return;
    int beg = off[w], end = off[w + 1];
    float adn = ad2[w];
    float ds = 0.f;
    for (int p = beg + l; p < end; p += 32)
        ds += __expf(lrelu(as2[srcv[p]] + adn));
#pragma unroll
    for (int o = 16; o > 0; o >>= 1) ds += __shfl_xor_sync(0xffffffffu, ds, o);
    float eself = __expf(lrelu(as2[w] + adn));
    ds += eself;
    float rden = 1.f / ds;
    const float2* h2 = (const float2*)gh;
    float2 acc = make_float2(0.f, 0.f);
    for (int p = beg; p < end; p++) {
        int s = srcv[p];
        float alpha = __expf(lrelu(as2[s] + adn)) * rden;
        float2 v = h2[s * 32 + l];
        acc.x += alpha * v.x; acc.y += alpha * v.y;
    }
    {
        float alpha = eself * rden;
        float2 v = h2[w * 32 + l];
        acc.x += alpha * v.x; acc.y += alpha * v.y;
    }
    ((float2*)out)[w * 32 + l] = acc;
}

__global__ void sage_node(const int* __restrict__ off, const int* __restrict__ srcv,
                          const float* __restrict__ h, float* __restrict__ out) {
    int w = (blockIdx.x * blockDim.x + threadIdx.x) >> 5;
    int l = threadIdx.x & 31;
    if (w >= NN) return;
    int beg = off[w], end = off[w + 1];
    const float2* h2 = (const float2*)h;
    float2 acc = make_float2(0.f, 0.f);
    for (int p = beg; p < end; p++) {
        float2 v = h2[srcv[p] * 32 + l];
        acc.x += v.x; acc.y += v.y;
    }
    float inv = 1.f / fmaxf((float)(end - beg), 1.f);
    acc.x *= inv; acc.y *= inv;
    ((float2*)out)[w * 32 + l] = acc;
}

__global__ void sage_post(const float* __restrict__ ml, const float* __restrict__ bl,
                          const float* __restrict__ xr, float* __restrict__ out, int dorelu) {
    int t = threadIdx.x;
    int w = t >> 5, l = t & 31;
    int n = blockIdx.x * 8 + w;
    float v0 = ml[n * 64 + l] + bl[l] + xr[n * 64 + l];
    float v1 = ml[n * 64 + 32 + l] + bl[32 + l] + xr[n * 64 + 32 + l];
    float ss = v0 * v0 + v1 * v1;
    for (int o = 16; o > 0; o >>= 1) ss += __shfl_xor_sync(0xffffffffu, ss, o);
    float inv = 1.f / fmaxf(sqrtf(ss), 1e-12f);
    float o0 = v0 * inv, o1 = v1 * inv;
    if (dorelu) { o0 = fmaxf(o0, 0.f); o1 = fmaxf(o1, 0.f); }
    out[n * 64 + l] = o0;
    out[n * 64 + 32 + l] = o1;
}

// ================= final combine =================
__global__ void combine_kernel(float4* __restrict__ out, const float* __restrict__ gate,
                               const float4* __restrict__ agg2, const float4* __restrict__ gagg2,
                               const float4* __restrict__ sout,
                               const float4* __restrict__ gcn_b2, const float4* __restrict__ gat_b2) {
    int i = blockIdx.x * 256 + threadIdx.x;   // NN*16 float4
    if (i >= NN * 16) return;
    int f = i & 15;
    float w0 = gate[0], w1 = gate[1], w2 = gate[2];
    float4 b0 = gcn_b2[f], b1 = gat_b2[f];
    float4 a = agg2[i], g = gagg2[i], s = sout[i];
    float4 o;
    o.x = w0 * (a.x + b0.x) + w1 * (g.x + b1.x) + w2 * s.x;
    o.y = w0 * (a.y + b0.y) + w1 * (g.y + b1.y) + w2 * s.y;
    o.z = w0 * (a.z + b0.z) + w1 * (g.z + b1.z) + w2 * s.z;
    o.w = w0 * (a.w + b0.w) + w1 * (g.w + b1.w) + w2 * s.w;
    out[i] = o;
}

// ================= launch (single stream; capture-safe) =================
extern "C" void kernel_launch(void* const* d_in, const int* in_sizes, int n_in,
                              void* d_out, int out_size) {
    const float* x        = (const float*)d_in[0];
    const int*   ei       = (const int*)d_in[1];
    const float* gate_w1  = (const float*)d_in[2];
    const float* gate_b1  = (const float*)d_in[3];
    const float* gate_w2  = (const float*)d_in[4];
    const float* gate_b2  = (const float*)d_in[5];
    const float* gcn_w1   = (const float*)d_in[6];
    const float* gcn_b1   = (const float*)d_in[7];
    const float* bn_gamma = (const float*)d_in[8];
    const float* bn_beta  = (const float*)d_in[9];
    const float* gcn_w2   = (const float*)d_in[10];
    const float* gcn_b2   = (const float*)d_in[11];
    const float* gat_w1   = (const float*)d_in[12];
    const float* gat_as1  = (const float*)d_in[13];
    const float* gat_ad1  = (const float*)d_in[14];
    const float* gat_b1   = (const float*)d_in[15];
    const float* gat_w2   = (const float*)d_in[16];
    const float* gat_as2  = (const float*)d_in[17];
    const float* gat_ad2  = (const float*)d_in[18];
    const float* gat_b2   = (const float*)d_in[19];
    const float* sage_wl1 = (const float*)d_in[20];
    const float* sage_bl1 = (const float*)d_in[21];
    const float* sage_wr1 = (const float*)d_in[22];
    const float* sage_wl2 = (const float*)d_in[23];
    const float* sage_bl2 = (const float*)d_in[24];
    const float* sage_wr2 = (const float*)d_in[25];
    float* out = (float*)d_out;

    float* B = nullptr;
    cudaGetSymbolAddress((void**)&B, g_buf);

    int*   ecnt   = (int*)(B + O_ECNT);
    float* gsum   = B + O_GSUM;
    float* gate   = B + O_GATE;
    float* dis    = B + O_DIS;
    int*   off    = (int*)(B + O_OFF);
    int*   cur    = (int*)(B + O_CUR);
    int*   srcv   = (int*)(B + O_SRC);
    int*   bsum   = (int*)(B + O_BSUM);
    int*   boff   = (int*)(B + O_BOFF);
    float* gcnxh  = B + O_GCNXH;
    float* gcnh1  = B + O_GCNH1;
    float* gcnh2  = B + O_GCNH2;
    float* agg2   = B + O_AGG2;
    float* gath1  = B + O_GATH1;
    float* as1    = B + O_AS1;
    float* ad1    = B + O_AD1;
    float* gagg1  = B + O_GAGG1;
    float* gath2  = B + O_GATH2;
    float* as2    = B + O_AS2;
    float* ad2    = B + O_AD2;
    float* gagg2  = B + O_GAGG2;
    float* sxr    = B + O_SXR;
    float* smean  = B + O_SMEAN;
    float* sml    = B + O_SML;
    float* sh1    = B + O_SH1;
    float* smean2 = B + O_SMEAN2;
    float* sml2   = B + O_SML2;
    float* sxr2   = B + O_SXR2;
    float* sout   = B + O_SOUT;

    const int* rowp = ei;
    const int* colp = ei + NE;

    const int GB = (NN + 127) / 128;          // gemm row-tiles (128 rows)
    const int WPB = (NN * 32 + 255) / 256;    // warp-per-node grids

    // zero edge counters + gate colsum accumulator (~200 KB)
    cudaMemsetAsync(B, 0, (size_t)ZEND * sizeof(float), 0);

    // ---- CSR build ----
    degree_kernel<<<(NE + 255) / 256, 256>>>(colp, ecnt);
    scan_bsum<<<NB, 256>>>(ecnt, bsum);
    scan_boff<<<1, 256>>>(bsum, boff);
    scan_final<<<NB, 256>>>(ecnt, boff, off, cur);
    scatter_kernel<<<(NE + 255) / 256, 256>>>(rowp, colp, off, cur, srcv);
    dis_kernel<<<(NN + 255) / 256, 256>>>(off, dis);

    // ---- gate ----
    colsum_kernel<<<512, 256>>>(x, gsum);
    gate_kernel<<<1, 64>>>(gsum, gate, gate_w1, gate_b1, gate_w2, gate_b2);

    // ---- feature transforms of x (one fused launch: 6 col-tiles) ----
    gemm_x3<<<dim3(GB, 6), 256>>>(x, gcn_w1, gcnxh, gat_w1, gath1, sage_wr1, sxr);

    // ---- GCN ----
    gcn_node<1><<<WPB, 256>>>(off, srcv, dis, gcnxh, gcnh1, gcn_b1, bn_gamma, bn_beta);
    gemm_tile<<<dim3(GB, 1), 256>>>(gcnh1, gcn_w2, gcnh2, NN, 64, 64);
    gcn_node<0><<<WPB, 256>>>(off, srcv, dis, gcnh2, agg2, 0, 0, 0);

    // ---- GAT ----
    gat_att1<<<NN / 8, 256>>>(gath1, as1, ad1, gat_as1, gat_ad1);
    gat1_node<<<WPB, 256>>>(off, srcv, as1, ad1, gath1, gagg1, gat_b1);
    gemm_tile<<<dim3(GB, 1), 256>>>(gagg1, gat_w2, gath2, NN, 256, 64);
    gat_att2<<<NN / 8, 256>>>(gath2, as2, ad2, gat_as2, gat_ad2);
    gat2_node<<<WPB, 256>>>(off, srcv, as2, ad2, gath2, gagg2);

    // ---- SAGE ----
    sage_node<<<WPB, 256>>>(off, srcv, x, smean);
    gemm_tile<<<dim3(GB, 1), 256>>>(smean, sage_wl1, sml, NN, 64, 64);
    sage_post<<<NN / 8, 256>>>(sml, sage_bl1, sxr, sh1, 1);
    sage_node<<<WPB, 256>>>(off, srcv, sh1, smean2);
    gemm_sage2<<<dim3(GB, 2), 256>>>(smean2, sage_wl2, sml2, sh1, sage_wr2, sxr2);
    sage_post<<<NN / 8, 256>>>(sml2, sage_bl2, sxr2, sout, 0);

    // ---- combine ----
    combine_kernel<<<(NN * 16 + 255) / 256, 256>>>((float4*)out, gate,
                                                   (const float4*)agg2, (const float4*)gagg2,
                                                   (const float4*)sout,
                                                   (const float4*)gcn_b2, (const float4*)gat_b2);
}

// round 17
// speedup vs baseline: 1.0006x; 1.0006x over previous
#include <cuda_runtime.h>
#include <math.h>

#define NN 50000
#define NE 400000
#define NB 196   // ceil(NN/256) scan blocks

// ---------------- scratch layout (float/int aliased units of 4B) ----------
#define O_ECNT   0LL                      // int[NN]  (zeroed by memset)
#define O_GSUM   (O_ECNT + NN)            // float[64] (zeroed)
#define ZEND     (O_GSUM + 64)
#define O_GATE   (ZEND)
#define O_DIS    (O_GATE + 4)
#define O_OFF    (O_DIS  + NN)            // int[NN+1]
#define O_CUR    (O_OFF  + NN + 8)        // int[NN]
#define O_SRC    (O_CUR  + NN)            // int[NE]
#define O_BSUM   (O_SRC  + NE)            // int[256]
#define O_BOFF   (O_BSUM + 256)           // int[256]
#define O_GCNXH  (O_BOFF + 256)
#define O_GCNH1  (O_GCNXH + (long long)NN*64)
#define O_GCNH2  (O_GCNH1 + (long long)NN*64)
#define O_AGG2   (O_GCNH2 + (long long)NN*64)
#define O_GATH1  (O_AGG2  + (long long)NN*64)
#define O_AS1    (O_GATH1 + (long long)NN*256)
#define O_AD1    (O_AS1   + (long long)NN*4)
#define O_GAGG1  (O_AD1   + (long long)NN*4)
#define O_GATH2  (O_GAGG1 + (long long)NN*256)
#define O_AS2    (O_GATH2 + (long long)NN*64)
#define O_AD2    (O_AS2   + NN)
#define O_GAGG2  (O_AD2   + NN)
#define O_SXR    (O_GAGG2 + (long long)NN*64)
#define O_SMEAN  (O_SXR   + (long long)NN*64)
#define O_SML    (O_SMEAN + (long long)NN*64)
#define O_SH1    (O_SML   + (long long)NN*64)
#define O_SMEAN2 (O_SH1   + (long long)NN*64)
#define O_SML2   (O_SMEAN2+ (long long)NN*64)
#define O_SXR2   (O_SML2  + (long long)NN*64)
#define O_SOUT   (O_SXR2  + (long long)NN*64)
#define SZ_TOTAL (O_SOUT  + (long long)NN*64)

__device__ __align__(256) float g_buf[SZ_TOTAL];

__device__ __forceinline__ float lrelu(float x) { return x > 0.f ? x : 0.2f * x; }

// packed f32x2 FMA (Blackwell; ptxas never emits FFMA2 from C++)
#define FMA2(d, a, b) asm volatile("fma.rn.f32x2 %0, %1, %2, %0;" : "+l"(d) : "l"(a), "l"(b))
#define PACK2(p, a)   asm volatile("mov.b64 %0, {%1, %1};" : "=l"(p) : "f"(a))

// ================= CSR build =================
__global__ void degree_kernel(const int* __restrict__ col, int* __restrict__ ecnt) {
    int e = blockIdx.x * blockDim.x + threadIdx.x;
    if (e < NE) atomicAdd(&ecnt[col[e]], 1);
}

__global__ void scan_bsum(const int* __restrict__ ecnt, int* __restrict__ bsum) {
    __shared__ int s[256];
    int i = blockIdx.x * 256 + threadIdx.x;
    s[threadIdx.x] = (i < NN) ? ecnt[i] : 0;
    __syncthreads();
    for (int o = 128; o > 0; o >>= 1) {
        if (threadIdx.x < o) s[threadIdx.x] += s[threadIdx.x + o];
        __syncthreads();
    }
    if (threadIdx.x == 0) bsum[blockIdx.x] = s[0];
}

__global__ void scan_boff(const int* __restrict__ bsum, int* __restrict__ boff) {
    __shared__ int s[256];
    int t = threadIdx.x;
    int v = (t < NB) ? bsum[t] : 0;
    s[t] = v;
    __syncthreads();
    for (int o = 1; o < 256; o <<= 1) {
        int x = (t >= o) ? s[t - o] : 0;
        __syncthreads();
        s[t] += x;
        __syncthreads();
    }
    boff[t] = s[t] - v;   // exclusive
}

__global__ void scan_final(const int* __restrict__ ecnt, const int* __restrict__ boff,
                           int* __restrict__ off, int* __restrict__ cursor) {
    __shared__ int s[256];
    int t = threadIdx.x;
    int i = blockIdx.x * 256 + t;
    int v = (i < NN) ? ecnt[i] : 0;
    s[t] = v;
    __syncthreads();
    for (int o = 1; o < 256; o <<= 1) {
        int x = (t >= o) ? s[t - o] : 0;
        __syncthreads();
        s[t] += x;
        __syncthreads();
    }
    if (i < NN) { off[i] = boff[blockIdx.x] + s[t] - v; cursor[i] = 0; }
    if (i == 0) off[NN] = NE;
}

__global__ void scatter_kernel(const int* __restrict__ row, const int* __restrict__ col,
                               const int* __restrict__ off, int* __restrict__ cursor,
                               int* __restrict__ srcv) {
    int e = blockIdx.x * 256 + threadIdx.x;
    if (e >= NE) return;
    int c = col[e];
    int p = off[c] + atomicAdd(&cursor[c], 1);
    srcv[p] = row[e];
}

__global__ void dis_kernel(const int* __restrict__ off, float* __restrict__ dis) {
    int i = blockIdx.x * blockDim.x + threadIdx.x;
    if (i < NN) dis[i] = rsqrtf((float)(off[i + 1] - off[i]) + 1.f);
}

// ================= gate =================
__global__ void colsum_kernel(const float* __restrict__ x, float* __restrict__ gsum) {
    __shared__ float4 s[256];
    int t = threadIdx.x;
    int c4 = t & 15, rg = t >> 4;
    float4 acc = {0.f, 0.f, 0.f, 0.f};
    for (int i = blockIdx.x * 16 + rg; i < NN; i += gridDim.x * 16) {
        float4 v = ((const float4*)x)[i * 16 + c4];
        acc.x += v.x; acc.y += v.y; acc.z += v.z; acc.w += v.w;
    }
    s[t] = acc;
    __syncthreads();
    for (int st = 128; st >= 16; st >>= 1) {
        if (t < st) {
            s[t].x += s[t + st].x; s[t].y += s[t + st].y;
            s[t].z += s[t + st].z; s[t].w += s[t + st].w;
        }
        __syncthreads();
    }
    if (t < 16) {
        float4 v = s[t];
        atomicAdd(&gsum[t * 4 + 0], v.x);
        atomicAdd(&gsum[t * 4 + 1], v.y);
        atomicAdd(&gsum[t * 4 + 2], v.z);
        atomicAdd(&gsum[t * 4 + 3], v.w);
    }
}

__global__ void gate_kernel(const float* __restrict__ gsum, float* __restrict__ gate,
                            const float* __restrict__ w1, const float* __restrict__ b1,
                            const float* __restrict__ w2, const float* __restrict__ b2) {
    __shared__ float gm[64], hid[64], o[3];
    int t = threadIdx.x;
    gm[t] = gsum[t] / (float)NN;
    __syncthreads();
    float a = b1[t];
    for (int k = 0; k < 64; k++) a += gm[k] * w1[k * 64 + t];
    hid[t] = fmaxf(a, 0.f);
    __syncthreads();
    if (t < 3) {
        float s = b2[t];
        for (int k = 0; k < 64; k++) s += hid[k] * w2[k * 3 + t];
        o[t] = s;
    }
    __syncthreads();
    if (t == 0) {
        float mx = fmaxf(o[0], fmaxf(o[1], o[2]));
        float e0 = expf(o[0] - mx), e1 = expf(o[1] - mx), e2 = expf(o[2] - mx);
        float s = e0 + e1 + e2;
        gate[0] = e0 / s; gate[1] = e1 / s; gate[2] = e2 / s;
    }
}

// ================= GEMM body: 128x64 tile, 256 thr, FFMA2 inner loop =======
// thread: 4 rows (rowg=t>>3) x 8 cols (colg=t&7), acc packed as u64 pairs.
// sA padded to 65 floats/row -> conflict-free broadcast reads.
__device__ __forceinline__ void gemm_body(
        const float* __restrict__ A, const float* __restrict__ W,
        float* __restrict__ C, int n, int din, int dout, int bx, int by) {
    __shared__ float sW[64 * 64];
    __shared__ float sA[128 * 65];
    int t = threadIdx.x;
    int colg = t & 7;        // 8 col groups of 8 cols
    int rowg = t >> 3;       // 32 row groups of 4 rows
    int r0 = bx * 128;
    int cb = by * 64;
    unsigned sWu = (unsigned)__cvta_generic_to_shared(sW);
    unsigned long long acc[4][4];
#pragma unroll
    for (int i = 0; i < 4; i++)
#pragma unroll
        for (int j = 0; j < 4; j++) acc[i][j] = 0ull;

    for (int k0 = 0; k0 < din; k0 += 64) {
#pragma unroll
        for (int u = 0; u < 4; u++) {
            int i = t + u * 256;
            int kk = i >> 4, cc = i & 15;
            ((float4*)sW)[i] = ((const float4*)(W + (long long)(k0 + kk) * dout + cb))[cc];
        }
#pragma unroll
        for (int u = 0; u < 8; u++) {
            int i = t + u * 256;
            int rr = i >> 4, kk = i & 15;
            float4 v = make_float4(0.f, 0.f, 0.f, 0.f);
            if (r0 + rr < n) v = ((const float4*)(A + (long long)(r0 + rr) * din + k0))[kk];
            float* dst = sA + rr * 65 + kk * 4;
            dst[0] = v.x; dst[1] = v.y; dst[2] = v.z; dst[3] = v.w;
        }
        __syncthreads();
#pragma unroll 8
        for (int k = 0; k < 64; k++) {
            unsigned long long w0, w1, w2, w3;
            unsigned waddr = sWu + (unsigned)((k * 64 + colg * 8) * 4);
            asm volatile("ld.shared.v2.u64 {%0,%1}, [%2];" : "=l"(w0), "=l"(w1) : "r"(waddr));
            asm volatile("ld.shared.v2.u64 {%0,%1}, [%2];" : "=l"(w2), "=l"(w3) : "r"(waddr + 16));
            const float* arow = sA + (rowg * 4) * 65 + k;
#pragma unroll
            for (int r = 0; r < 4; r++) {
                unsigned long long ap;
                PACK2(ap, arow[r * 65]);
                FMA2(acc[r][0], ap, w0);
                FMA2(acc[r][1], ap, w1);
                FMA2(acc[r][2], ap, w2);
                FMA2(acc[r][3], ap, w3);
            }
        }
        __syncthreads();
    }
#pragma unroll
    for (int r = 0; r < 4; r++) {
        int row = r0 + rowg * 4 + r;
        if (row < n) {
            ulonglong2* dst = (ulonglong2*)(C + (long long)row * dout + cb + colg * 8);
            dst[0] = make_ulonglong2(acc[r][0], acc[r][1]);
            dst[1] = make_ulonglong2(acc[r][2], acc[r][3]);
        }
    }
}

__global__ void __launch_bounds__(256) gemm_tile(
        const float* __restrict__ A, const float* __restrict__ W,
        float* __restrict__ C, int n, int din, int dout) {
    gemm_body(A, W, C, n, din, dout, blockIdx.x, blockIdx.y);
}

// fused: the three independent x-transforms in one launch (blockIdx.y dispatch)
__global__ void __launch_bounds__(256) gemm_x3(
        const float* __restrict__ x,
        const float* __restrict__ w_gcn, float* __restrict__ o_gcn,
        const float* __restrict__ w_gat, float* __restrict__ o_gat,
        const float* __restrict__ w_sage, float* __restrict__ o_sage) {
    int y = blockIdx.y;
    if (y == 0)      gemm_body(x, w_gcn,  o_gcn,  NN, 64, 64,  blockIdx.x, 0);
    else if (y <= 4) gemm_body(x, w_gat,  o_gat,  NN, 64, 256, blockIdx.x, y - 1);
    else             gemm_body(x, w_sage, o_sage, NN, 64, 64,  blockIdx.x, 0);
}

// fused: the two independent SAGE layer-2 GEMMs
__global__ void __launch_bounds__(256) gemm_sage2(
        const float* __restrict__ smean2, const float* __restrict__ wl2, float* __restrict__ sml2,
        const float* __restrict__ sh1,    const float* __restrict__ wr2, float* __restrict__ sxr2) {
    if (blockIdx.y == 0) gemm_body(smean2, wl2, sml2, NN, 64, 64, blockIdx.x, 0);
    else                 gemm_body(sh1,    wr2, sxr2, NN, 64, 64, blockIdx.x, 0);
}

// ================= per-node aggregations (warp per node) =================
template <int EPI>
__global__ void gcn_node(const int* __restrict__ off, const int* __restrict__ srcv,
                         const float* __restrict__ dis, const float* __restrict__ h,
                         float* __restrict__ out, const float* __restrict__ b,
                         const float* __restrict__ gamma, const float* __restrict__ beta) {
    int w = (blockIdx.x * blockDim.x + threadIdx.x) >> 5;
    int l = threadIdx.x & 31;
    if (w >= NN) return;
    int beg = off[w], end = off[w + 1];
    float dn = dis[w];
    const float2* h2 = (const float2*)h;
    float2 acc = make_float2(0.f, 0.f);
    for (int p = beg; p < end; p++) {
        int s = srcv[p];
        float ds = dis[s];
        float2 v = h2[s * 32 + l];
        acc.x += v.x * ds; acc.y += v.y * ds;
    }
    float2 hs = h2[w * 32 + l];
    acc.x = (acc.x + dn * hs.x) * dn;
    acc.y = (acc.y + dn * hs.y) * dn;
    if (EPI) {
        float sc = rsqrtf(1.f + 1e-5f);
        float b0 = b[l * 2], b1 = b[l * 2 + 1];
        float g0 = gamma[l * 2] * sc, g1 = gamma[l * 2 + 1] * sc;
        float t0 = beta[l * 2], t1 = beta[l * 2 + 1];
        acc.x = fmaxf((acc.x + b0) * g0 + t0, 0.f);
        acc.y = fmaxf((acc.y + b1) * g1 + t1, 0.f);
    }
    ((float2*)out)[w * 32 + l] = acc;
}

__global__ void gat_att1(const float* __restrict__ gath1,
                         float* __restrict__ as1, float* __restrict__ ad1,
                         const float* __restrict__ asrc, const float* __restrict__ adst) {
    int t = threadIdx.x;
    int w = t >> 5, l = t & 31;
    int n = blockIdx.x * 8 + w;
    const float4* g4 = (const float4*)(gath1 + (long long)n * 256);
    float4 a = g4[l * 2], b = g4[l * 2 + 1];
    int h = l >> 3;
    int offv = (l & 7) * 8;
    const float* As = asrc + h * 64 + offv;
    const float* Ad = adst + h * 64 + offv;
    float ss = a.x*As[0] + a.y*As[1] + a.z*As[2] + a.w*As[3]
             + b.x*As[4] + b.y*As[5] + b.z*As[6] + b.w*As[7];
    float sd = a.x*Ad[0] + a.y*Ad[1] + a.z*Ad[2] + a.w*Ad[3]
             + b.x*Ad[4] + b.y*Ad[5] + b.z*Ad[6] + b.w*Ad[7];
    ss += __shfl_xor_sync(0xffffffffu, ss, 1);
    sd += __shfl_xor_sync(0xffffffffu, sd, 1);
    ss += __shfl_xor_sync(0xffffffffu, ss, 2);
    sd += __shfl_xor_sync(0xffffffffu, sd, 2);
    ss += __shfl_xor_sync(0xffffffffu, ss, 4);
    sd += __shfl_xor_sync(0xffffffffu, sd, 4);
    if ((l & 7) == 0) { as1[n * 4 + h] = ss; ad1[n * 4 + h] = sd; }
}

__device__ __forceinline__ float4 exp_lrelu4(float4 s, float4 d) {
    float4 o;
    o.x = __expf(lrelu(s.x + d.x));
    o.y = __expf(lrelu(s.y + d.y));
    o.z = __expf(lrelu(s.z + d.z));
    o.w = __expf(lrelu(s.w + d.w));
    return o;
}
__device__ __forceinline__ float sel4(float4 v, int h) {
    float r = v.x;
    r = (h == 1) ? v.y : r;
    r = (h == 2) ? v.z : r;
    r = (h == 3) ? v.w : r;
    return r;
}

__global__ void gat1_node(const int* __restrict__ off, const int* __restrict__ srcv,
                          const float* __restrict__ as1, const float* __restrict__ ad1,
                          const float* __restrict__ gh, float* __restrict__ out,
                          const float* __restrict__ bias) {
    int w = (blockIdx.x * blockDim.x + threadIdx.x) >> 5;
    int l = threadIdx.x & 31;
    if (w >= NN) return;
    int beg = off[w], end = off[w + 1];
    const float4* as4 = (const float4*)as1;
    float4 adn = ((const float4*)ad1)[w];
    float4 ds = make_float4(0.f, 0.f, 0.f, 0.f);
    for (int p = beg + l; p < end; p += 32) {
        float4 e4 = exp_lrelu4(as4[srcv[p]], adn);
        ds.x += e4.x; ds.y += e4.y; ds.z += e4.z; ds.w += e4.w;
    }
#pragma unroll
    for (int o = 16; o > 0; o >>= 1) {
        ds.x += __shfl_xor_sync(0xffffffffu, ds.x, o);
        ds.y += __shfl_xor_sync(0xffffffffu, ds.y, o);
        ds.z += __shfl_xor_sync(0xffffffffu, ds.z, o);
        ds.w += __shfl_xor_sync(0xffffffffu, ds.w, o);
    }
    float4 eself = exp_lrelu4(as4[w], adn);
    ds.x += eself.x; ds.y += eself.y; ds.z += eself.z; ds.w += eself.w;
    int h = l >> 3;
    float rden = 1.f / sel4(ds, h);
    float adh = sel4(adn, h);
    float4 a0 = make_float4(0.f, 0.f, 0.f, 0.f), a1 = a0;
    for (int p = beg; p < end; p++) {
        int s = srcv[p];
        float e = __expf(lrelu(sel4(as4[s], h) + adh));
        float alpha = e * rden;
        const float4* gr = (const float4*)(gh + (long long)s * 256) + l * 2;
        float4 v0 = gr[0], v1 = gr[1];
        a0.x += alpha * v0.x; a0.y += alpha * v0.y; a0.z += alpha * v0.z; a0.w += alpha * v0.w;
        a1.x += alpha * v1.x; a1.y += alpha * v1.y; a1.z += alpha * v1.z; a1.w += alpha * v1.w;
    }
    {
        float alpha = sel4(eself, h) * rden;
        const float4* gr = (const float4*)(gh + (long long)w * 256) + l * 2;
        float4 v0 = gr[0], v1 = gr[1];
        a0.x += alpha * v0.x; a0.y += alpha * v0.y; a0.z += alpha * v0.z; a0.w += alpha * v0.w;
        a1.x += alpha * v1.x; a1.y += alpha * v1.y; a1.z += alpha * v1.z; a1.w += alpha * v1.w;
    }
    const float4* b4 = (const float4*)bias + l * 2;
    float4 bb0 = b4[0], bb1 = b4[1];
    a0.x += bb0.x; a0.y += bb0.y; a0.z += bb0.z; a0.w += bb0.w;
    a1.x += bb1.x; a1.y += bb1.y; a1.z += bb1.z; a1.w += bb1.w;
    a0.x = a0.x > 0.f ? a0.x : (expf(a0.x) - 1.f);
    a0.y = a0.y > 0.f ? a0.y : (expf(a0.y) - 1.f);
    a0.z = a0.z > 0.f ? a0.z : (expf(a0.z) - 1.f);
    a0.w = a0.w > 0.f ? a0.w : (expf(a0.w) - 1.f);
    a1.x = a1.x > 0.f ? a1.x : (expf(a1.x) - 1.f);
    a1.y = a1.y > 0.f ? a1.y : (expf(a1.y) - 1.f);
    a1.z = a1.z > 0.f ? a1.z : (expf(a1.z) - 1.f);
    a1.w = a1.w > 0.f ? a1.w : (expf(a1.w) - 1.f);
    float4* o4 = (float4*)(out + (long long)w * 256) + l * 2;
    o4[0] = a0; o4[1] = a1;
}

__global__ void gat_att2(const float* __restrict__ gath2,
                         float* __restrict__ as2, float* __restrict__ ad2,
                         const float* __restrict__ asrc, const float* __restrict__ adst) {
    int t = threadIdx.x;
    int w = t >> 5, l = t & 31;
    int n = blockIdx.x * 8 + w;
    float v0 = gath2[n * 64 + l], v1 = gath2[n * 64 + 32 + l];
    float ss = v0 * asrc[l] + v1 * asrc[32 + l];
    float sd = v0 * adst[l] + v1 * adst[32 + l];
    for (int o = 16; o > 0; o >>= 1) {
        ss += __shfl_xor_sync(0xffffffffu, ss, o);
        sd += __shfl_xor_sync(0xffffffffu, sd, o);
    }
    if (l == 0) { as2[n] = ss; ad2[n] = sd; }
}

__global__ void gat2_node(const int* __restrict__ off, const int* __restrict__ srcv,
                          const float* __restrict__ as2, const float* __restrict__ ad2,
                          const float* __restrict__ gh, float* __restrict__ out) {
    int w = (blockIdx.x * blockDim.x + threadIdx.x) >> 5;
    int l = threadIdx.x & 31;
    if (w >= NN) return;
    int beg = off[w], end = off[w + 1];
    float adn = ad2[w];
    float ds = 0.f;
    for (int p = beg + l; p < end; p += 32)
        ds += __expf(lrelu(as2[srcv[p]] + adn));
#pragma unroll
    for (int o = 16; o > 0; o >>= 1) ds += __shfl_xor_sync(0xffffffffu, ds, o);
    float eself = __expf(lrelu(as2[w] + adn));
    ds += eself;
    float rden = 1.f / ds;
    const float2* h2 = (const float2*)gh;
    float2 acc = make_float2(0.f, 0.f);
    for (int p = beg; p < end; p++) {
        int s = srcv[p];
        float alpha = __expf(lrelu(as2[s] + adn)) * rden;
        float2 v = h2[s * 32 + l];
        acc.x += alpha * v.x; acc.y += alpha * v.y;
    }
    {
        float alpha = eself * rden;
        float2 v = h2[w * 32 + l];
        acc.x += alpha * v.x; acc.y += alpha * v.y;
    }
    ((float2*)out)[w * 32 + l] = acc;
}

__global__ void sage_node(const int* __restrict__ off, const int* __restrict__ srcv,
                          const float* __restrict__ h, float* __restrict__ out) {
    int w = (blockIdx.x * blockDim.x + threadIdx.x) >> 5;
    int l = threadIdx.x & 31;
    if (w >= NN) return;
    int beg = off[w], end = off[w + 1];
    const float2* h2 = (const float2*)h;
    float2 acc = make_float2(0.f, 0.f);
    for (int p = beg; p < end; p++) {
        float2 v = h2[srcv[p] * 32 + l];
        acc.x += v.x; acc.y += v.y;
    }
    float inv = 1.f / fmaxf((float)(end - beg), 1.f);
    acc.x *= inv; acc.y *= inv;
    ((float2*)out)[w * 32 + l] = acc;
}

__global__ void sage_post(const float* __restrict__ ml, const float* __restrict__ bl,
                          const float* __restrict__ xr, float* __restrict__ out, int dorelu) {
    int t = threadIdx.x;
    int w = t >> 5, l = t & 31;
    int n = blockIdx.x * 8 + w;
    float v0 = ml[n * 64 + l] + bl[l] + xr[n * 64 + l];
    float v1 = ml[n * 64 + 32 + l] + bl[32 + l] + xr[n * 64 + 32 + l];
    float ss = v0 * v0 + v1 * v1;
    for (int o = 16; o > 0; o >>= 1) ss += __shfl_xor_sync(0xffffffffu, ss, o);
    float inv = 1.f / fmaxf(sqrtf(ss), 1e-12f);
    float o0 = v0 * inv, o1 = v1 * inv;
    if (dorelu) { o0 = fmaxf(o0, 0.f); o1 = fmaxf(o1, 0.f); }
    out[n * 64 + l] = o0;
    out[n * 64 + 32 + l] = o1;
}

// ================= final combine =================
__global__ void combine_kernel(float4* __restrict__ out, const float* __restrict__ gate,
                               const float4* __restrict__ agg2, const float4* __restrict__ gagg2,
                               const float4* __restrict__ sout,
                               const float4* __restrict__ gcn_b2, const float4* __restrict__ gat_b2) {
    int i = blockIdx.x * 256 + threadIdx.x;   // NN*16 float4
    if (i >= NN * 16) return;
    int f = i & 15;
    float w0 = gate[0], w1 = gate[1], w2 = gate[2];
    float4 b0 = gcn_b2[f], b1 = gat_b2[f];
    float4 a = agg2[i], g = gagg2[i], s = sout[i];
    float4 o;
    o.x = w0 * (a.x + b0.x) + w1 * (g.x + b1.x) + w2 * s.x;
    o.y = w0 * (a.y + b0.y) + w1 * (g.y + b1.y) + w2 * s.y;
    o.z = w0 * (a.z + b0.z) + w1 * (g.z + b1.z) + w2 * s.z;
    o.w = w0 * (a.w + b0.w) + w1 * (g.w + b1.w) + w2 * s.w;
    out[i] = o;
}

// ================= launch (single stream; capture-safe) =================
extern "C" void kernel_launch(void* const* d_in, const int* in_sizes, int n_in,
                              void* d_out, int out_size) {
    const float* x        = (const float*)d_in[0];
    const int*   ei       = (const int*)d_in[1];
    const float* gate_w1  = (const float*)d_in[2];
    const float* gate_b1  = (const float*)d_in[3];
    const float* gate_w2  = (const float*)d_in[4];
    const float* gate_b2  = (const float*)d_in[5];
    const float* gcn_w1   = (const float*)d_in[6];
    const float* gcn_b1   = (const float*)d_in[7];
    const float* bn_gamma = (const float*)d_in[8];
    const float* bn_beta  = (const float*)d_in[9];
    const float* gcn_w2   = (const float*)d_in[10];
    const float* gcn_b2   = (const float*)d_in[11];
    const float* gat_w1   = (const float*)d_in[12];
    const float* gat_as1  = (const float*)d_in[13];
    const float* gat_ad1  = (const float*)d_in[14];
    const float* gat_b1   = (const float*)d_in[15];
    const float* gat_w2   = (const float*)d_in[16];
    const float* gat_as2  = (const float*)d_in[17];
    const float* gat_ad2  = (const float*)d_in[18];
    const float* gat_b2   = (const float*)d_in[19];
    const float* sage_wl1 = (const float*)d_in[20];
    const float* sage_bl1 = (const float*)d_in[21];
    const float* sage_wr1 = (const float*)d_in[22];
    const float* sage_wl2 = (const float*)d_in[23];
    const float* sage_bl2 = (const float*)d_in[24];
    const float* sage_wr2 = (const float*)d_in[25];
    float* out = (float*)d_out;

    float* B = nullptr;
    cudaGetSymbolAddress((void**)&B, g_buf);

    int*   ecnt   = (int*)(B + O_ECNT);
    float* gsum   = B + O_GSUM;
    float* gate   = B + O_GATE;
    float* dis    = B + O_DIS;
    int*   off    = (int*)(B + O_OFF);
    int*   cur    = (int*)(B + O_CUR);
    int*   srcv   = (int*)(B + O_SRC);
    int*   bsum   = (int*)(B + O_BSUM);
    int*   boff   = (int*)(B + O_BOFF);
    float* gcnxh  = B + O_GCNXH;
    float* gcnh1  = B + O_GCNH1;
    float* gcnh2  = B + O_GCNH2;
    float* agg2   = B + O_AGG2;
    float* gath1  = B + O_GATH1;
    float* as1    = B + O_AS1;
    float* ad1    = B + O_AD1;
    float* gagg1  = B + O_GAGG1;
    float* gath2  = B + O_GATH2;
    float* as2    = B + O_AS2;
    float* ad2    = B + O_AD2;
    float* gagg2  = B + O_GAGG2;
    float* sxr    = B + O_SXR;
    float* smean  = B + O_SMEAN;
    float* sml    = B + O_SML;
    float* sh1    = B + O_SH1;
    float* smean2 = B + O_SMEAN2;
    float* sml2   = B + O_SML2;
    float* sxr2   = B + O_SXR2;
    float* sout   = B + O_SOUT;

    const int* rowp = ei;
    const int* colp = ei + NE;

    const int GB = (NN + 127) / 128;          // gemm row-tiles (128 rows)
    const int WPB = (NN * 32 + 255) / 256;    // warp-per-node grids

    // zero edge counters + gate colsum accumulator (~200 KB)
    cudaMemsetAsync(B, 0, (size_t)ZEND * sizeof(float), 0);

    // ---- CSR build ----
    degree_kernel<<<(NE + 255) / 256, 256>>>(colp, ecnt);
    scan_bsum<<<NB, 256>>>(ecnt, bsum);
    scan_boff<<<1, 256>>>(bsum, boff);
    scan_final<<<NB, 256>>>(ecnt, boff, off, cur);
    scatter_kernel<<<(NE + 255) / 256, 256>>>(rowp, colp, off, cur, srcv);
    dis_kernel<<<(NN + 255) / 256, 256>>>(off, dis);

    // ---- gate ----
    colsum_kernel<<<512, 256>>>(x, gsum);
    gate_kernel<<<1, 64>>>(gsum, gate, gate_w1, gate_b1, gate_w2, gate_b2);

    // ---- feature transforms of x (one fused launch: 6 col-tiles) ----
    gemm_x3<<<dim3(GB, 6), 256>>>(x, gcn_w1, gcnxh, gat_w1, gath1, sage_wr1, sxr);

    // ---- GCN ----
    gcn_node<1><<<WPB, 256>>>(off, srcv, dis, gcnxh, gcnh1, gcn_b1, bn_gamma, bn_beta);
    gemm_tile<<<dim3(GB, 1), 256>>>(gcnh1, gcn_w2, gcnh2, NN, 64, 64);
    gcn_node<0><<<WPB, 256>>>(off, srcv, dis, gcnh2, agg2, 0, 0, 0);

    // ---- GAT ----
    gat_att1<<<NN / 8, 256>>>(gath1, as1, ad1, gat_as1, gat_ad1);
    gat1_node<<<WPB, 256>>>(off, srcv, as1, ad1, gath1, gagg1, gat_b1);
    gemm_tile<<<dim3(GB, 1), 256>>>(gagg1, gat_w2, gath2, NN, 256, 64);
    gat_att2<<<NN / 8, 256>>>(gath2, as2, ad2, gat_as2, gat_ad2);
    gat2_node<<<WPB, 256>>>(off, srcv, as2, ad2, gath2, gagg2);

    // ---- SAGE ----
    sage_node<<<WPB, 256>>>(off, srcv, x, smean);
    gemm_tile<<<dim3(GB, 1), 256>>>(smean, sage_wl1, sml, NN, 64, 64);
    sage_post<<<NN / 8, 256>>>(sml, sage_bl1, sxr, sh1, 1);
    sage_node<<<WPB, 256>>>(off, srcv, sh1, smean2);
    gemm_sage2<<<dim3(GB, 2), 256>>>(smean2, sage_wl2, sml2, sh1, sage_wr2, sxr2);
    sage_post<<<NN / 8, 256>>>(sml2, sage_bl2, sxr2, sout, 0);

    // ---- combine ----
    combine_kernel<<<(NN * 16 + 255) / 256, 256>>>((float4*)out, gate,
                                                   (const float4*)agg2, (const float4*)gagg2,
                                                   (const float4*)sout,
                                                   (const float4*)gcn_b2, (const float4*)gat_b2);
}